// round 3
// baseline (speedup 1.0000x reference)
#include <cuda_runtime.h>

// Problem constants
#define BB 128      // batch
#define DD 128      // dim
#define NN 16384    // prototypes
#define NCC 100     // classes
#define CN 128      // n-chunk per block
#define NBLK (NN / CN)   // 128
#define PAD 132     // smem row pad (floats): 132*4=528, 16B-aligned rows
#define CROW 104    // C tile row: 100 classes + ones col + pad

// Scratch (static __device__ — no allocations allowed)
__device__ float g_xpT[DD * BB];          // Xp transposed [d][b]
__device__ float g_y2[BB];
__device__ float g_part[NBLK * BB * NCC]; // per-chunk numerator partials
__device__ float g_pden[NBLK * BB];       // per-chunk denominator partials

// ---------------------------------------------------------------------------
// Kernel 1: project X onto the Poincare ball, write transposed Xp and y2
// grid(128 blocks = one per row b), 128 threads = one per d
// ---------------------------------------------------------------------------
__global__ void proj_kernel(const float* __restrict__ X) {
    int b = blockIdx.x;
    int d = threadIdx.x;
    float v = X[b * DD + d];
    float sq = v * v;
    #pragma unroll
    for (int o = 16; o > 0; o >>= 1) sq += __shfl_down_sync(0xffffffffu, sq, o);
    __shared__ float red[4];
    if ((d & 31) == 0) red[d >> 5] = sq;
    __syncthreads();
    float tot = red[0] + red[1] + red[2] + red[3];
    float norm = fmaxf(sqrtf(tot), 1e-15f);
    const float maxn = 1.0f - 4e-3f;
    float scale = (norm > maxn) ? (maxn / norm) : 1.0f;
    float xp = v * scale;
    g_xpT[d * BB + b] = xp;
    if (d == 0) g_y2[b] = scale * scale * tot;
}

// ---------------------------------------------------------------------------
// Kernel 2: per N-chunk: dot GEMM -> weights -> weighted-C GEMM partials
// grid(NBLK=128), 256 threads, dynamic smem
// smem layout:
//   bufA [128*PAD] : Xp^T tile (k-major), later C tile (rows of CROW=104)
//   bufB [128*PAD] : A^T tile (k-major),  later W tile [n][b]
//   sY2[128], sX2[128]
// ---------------------------------------------------------------------------
__global__ void __launch_bounds__(256, 1)
main_kernel(const float* __restrict__ A, const float* __restrict__ C) {
    extern __shared__ float sm[];
    float* bufA = sm;
    float* bufB = sm + 128 * PAD;
    float* sY2  = sm + 2 * 128 * PAD;
    float* sX2  = sY2 + 128;

    const int t   = threadIdx.x;
    const int blk = blockIdx.x;
    const int n0  = blk * CN;

    // Load Xp^T straight (already k-major) and A chunk transposed into smem
    {
        const float* Ab = A + (long)n0 * DD;
        #pragma unroll 4
        for (int j = 0; j < 64; ++j) {
            int i = t + j * 256;           // 0..16383
            int r = i >> 7;                // row (d for Xp, n for A)
            int c = i & 127;               // col (b for Xp, k for A)
            bufA[r * PAD + c] = g_xpT[i];  // sXt[k=d][b]
            bufB[c * PAD + r] = Ab[i];     // sAt[k][n]
        }
        if (t < 128) sY2[t] = g_y2[t];
    }
    __syncthreads();

    // x2[n] = |A[n]|^2 from the transposed tile (column read)
    if (t < 128) {
        float s = 0.f;
        #pragma unroll 8
        for (int k = 0; k < 128; ++k) { float v = bufB[k * PAD + t]; s = fmaf(v, v, s); }
        sX2[t] = s;
    }
    __syncthreads();

    // ---- GEMM1: dot[n][b], 8x8 register tile per thread ----
    const int tx = t & 15;        // b-tile:  b = tx*8 .. +7
    const int ty = t >> 4;        // n-tile:  n = ty*8 .. +7
    float acc[8][8];
    #pragma unroll
    for (int i = 0; i < 8; ++i)
        #pragma unroll
        for (int j = 0; j < 8; ++j) acc[i][j] = 0.f;

    #pragma unroll 2
    for (int k = 0; k < 128; ++k) {
        const float4 a0 = *(const float4*)(bufB + k * PAD + (ty << 3));
        const float4 a1 = *(const float4*)(bufB + k * PAD + (ty << 3) + 4);
        const float4 x0 = *(const float4*)(bufA + k * PAD + (tx << 3));
        const float4 x1 = *(const float4*)(bufA + k * PAD + (tx << 3) + 4);
        float av[8] = {a0.x, a0.y, a0.z, a0.w, a1.x, a1.y, a1.z, a1.w};
        float xv[8] = {x0.x, x0.y, x0.z, x0.w, x1.x, x1.y, x1.z, x1.w};
        #pragma unroll
        for (int i = 0; i < 8; ++i)
            #pragma unroll
            for (int j = 0; j < 8; ++j) acc[i][j] = fmaf(av[i], xv[j], acc[i][j]);
    }

    // ---- transform: dot -> weight = ((1-z)/(1+z))^(1/4) (in registers) ----
    float y2v[8];
    #pragma unroll
    for (int j = 0; j < 8; ++j) y2v[j] = sY2[(tx << 3) + j];
    #pragma unroll
    for (int i = 0; i < 8; ++i) {
        const float x2 = sX2[(ty << 3) + i];
        const float be = 1.f - x2;
        #pragma unroll
        for (int j = 0; j < 8; ++j) {
            const float y2 = y2v[j];
            const float xy = -acc[i][j];
            const float tp = fmaf(2.f, xy, 1.f);
            const float al = tp + y2;
            float den = fmaf(x2, y2, tp);
            den = fmaxf(den, 1e-15f);
            float num2 = al * al * x2 + 2.f * al * be * xy + be * be * y2;
            float z = sqrtf(fmaxf(num2, 0.f)) / den;
            z = fminf(z, 1.f - 1e-7f);
            float r = (1.f - z) / (1.f + z);
            acc[i][j] = sqrtf(sqrtf(r));    // exp(-dist/4), exact identity
        }
    }
    __syncthreads();   // all GEMM1 reads done; safe to repurpose both buffers

    // Store W[n][b] into bufB; load C chunk (+ones col) into bufA
    #pragma unroll
    for (int i = 0; i < 8; ++i) {
        float* wr = bufB + ((ty << 3) + i) * PAD + (tx << 3);
        *(float4*)(wr)     = make_float4(acc[i][0], acc[i][1], acc[i][2], acc[i][3]);
        *(float4*)(wr + 4) = make_float4(acc[i][4], acc[i][5], acc[i][6], acc[i][7]);
    }
    {
        const float* Cb = C + (long)n0 * NCC;
        #pragma unroll 4
        for (int j = 0; j < 52; ++j) {         // 52*256 = 13312 = 128*104
            int i = t + j * 256;
            int r = i / CROW;
            int c = i - r * CROW;
            float v = (c < NCC) ? Cb[r * NCC + c] : ((c == NCC) ? 1.0f : 0.0f);
            bufA[r * CROW + c] = v;
        }
    }
    __syncthreads();

    // ---- GEMM2: numer[b][c] = sum_n W[n][b] * C[n][c]; c==100 -> denom ----
    const int tx2 = t & 31;       // b = tx2*4 .. +3
    const int ty2 = t >> 5;       // c = ty2*13 .. +12 (covers 0..103)
    const int c0  = ty2 * 13;
    float acc2[4][13];
    #pragma unroll
    for (int bi = 0; bi < 4; ++bi)
        #pragma unroll
        for (int j = 0; j < 13; ++j) acc2[bi][j] = 0.f;

    #pragma unroll 2
    for (int n = 0; n < 128; ++n) {
        const float4 w4 = *(const float4*)(bufB + n * PAD + (tx2 << 2));
        float wv[4] = {w4.x, w4.y, w4.z, w4.w};
        float cv[13];
        #pragma unroll
        for (int j = 0; j < 13; ++j) cv[j] = bufA[n * CROW + c0 + j];
        #pragma unroll
        for (int bi = 0; bi < 4; ++bi)
            #pragma unroll
            for (int j = 0; j < 13; ++j)
                acc2[bi][j] = fmaf(wv[bi], cv[j], acc2[bi][j]);
    }

    // Write partials (deterministic layout)
    #pragma unroll
    for (int bi = 0; bi < 4; ++bi) {
        const int b = (tx2 << 2) + bi;
        #pragma unroll
        for (int j = 0; j < 13; ++j) {
            const int c = c0 + j;
            if (c < NCC)       g_part[(long)blk * BB * NCC + b * NCC + c] = acc2[bi][j];
            else if (c == NCC) g_pden[blk * BB + b] = acc2[bi][j];
        }
    }
}

// ---------------------------------------------------------------------------
// Kernel 3: deterministic reduction over chunks + divide
// grid(128 = one per b), 128 threads (c = tid, active c<100)
// ---------------------------------------------------------------------------
__global__ void reduce_kernel(float* __restrict__ out) {
    int b = blockIdx.x;
    int c = threadIdx.x;
    float den = 0.f;
    #pragma unroll 8
    for (int k = 0; k < NBLK; ++k) den += g_pden[k * BB + b];
    if (c < NCC) {
        float s = 0.f;
        #pragma unroll 8
        for (int k = 0; k < NBLK; ++k) s += g_part[(long)k * BB * NCC + b * NCC + c];
        out[b * NCC + c] = s / den;
    }
}

// ---------------------------------------------------------------------------
extern "C" void kernel_launch(void* const* d_in, const int* in_sizes, int n_in,
                              void* d_out, int out_size) {
    const float* X = (const float*)d_in[0];
    const float* A = (const float*)d_in[1];
    const float* C = (const float*)d_in[2];
    float* out = (float*)d_out;

    const int smem_bytes = (2 * 128 * PAD + 256) * sizeof(float);  // 136,192 B

    // One-time config (host-side only; identical captured launches every call)
    static bool configured = false;
    if (!configured) {
        (void)cudaFuncSetAttribute(main_kernel,
                                   cudaFuncAttributeMaxDynamicSharedMemorySize,
                                   smem_bytes);
        configured = true;
    }

    proj_kernel<<<BB, DD>>>(X);
    main_kernel<<<NBLK, 256, smem_bytes>>>(A, C);
    reduce_kernel<<<BB, BB>>>(out);
}